// round 16
// baseline (speedup 1.0000x reference)
#include <cuda_runtime.h>
#include <cuda_fp16.h>
#include <cstdint>

#define NN_D 256          // feature dim D
#define KNEI 16           // neighbors per node

// fp16 support scratch: 50000*256*2 = 25.6 MB (L2-resident for agg)
__device__ __half g_support_h[50000 * 256];

// ---------------------------------------------------------------------------
// GEMM via mma.sync fp16, single MMA per fragment (A, B, support all fp16;
// independent 2^-11 roundings -> rel_err ~5.6e-4 < 1e-3, fp32 accumulate).
// Register-prefetch + DOUBLE-BUFFERED smem (1 sync/chunk) + 2 CTAs/SM.
// C[M,256] = A[M,256] @ W[256,256]^T + b_lin
// CTA tile 128x64 (8 warps = 4M x 2N, warp tile 32x32), KC=64.
// Grid is (bn, bm) so the 4 CTAs sharing an A-tile are launch-adjacent.
// ---------------------------------------------------------------------------
#define BM 128
#define BN 64
#define KC 64
#define LDS 72            // padded fp16 leading dim (conflict-free ldmatrix)

#define AS   0
#define BS   (BM * LDS * 2)                  // 18432
#define BUFB (BS + BN * LDS * 2)             // 27648 per buffer
#define SMEM_GEMM (2 * BUFB)                 // 55296

__device__ __forceinline__ uint32_t smem_u32(const void* p) {
    uint32_t a;
    asm("{ .reg .u64 t; cvta.to.shared.u64 t, %1; cvt.u32.u64 %0, t; }"
        : "=r"(a) : "l"(p));
    return a;
}

__device__ __forceinline__ uint32_t cvt_f16x2(float x, float y) {
    __half2 hh = __floats2half2_rn(x, y);
    return *reinterpret_cast<uint32_t*>(&hh);
}

__device__ __forceinline__ void ldm_x4(uint32_t& r0, uint32_t& r1, uint32_t& r2,
                                       uint32_t& r3, uint32_t addr) {
    asm volatile("ldmatrix.sync.aligned.m8n8.x4.shared.b16 {%0,%1,%2,%3}, [%4];"
                 : "=r"(r0), "=r"(r1), "=r"(r2), "=r"(r3) : "r"(addr));
}

__device__ __forceinline__ void mma16816(float* c, const uint32_t* a, const uint32_t* b) {
    asm volatile(
        "mma.sync.aligned.m16n8k16.row.col.f32.f16.f16.f32 "
        "{%0,%1,%2,%3}, {%4,%5,%6,%7}, {%8,%9}, {%0,%1,%2,%3};"
        : "+f"(c[0]), "+f"(c[1]), "+f"(c[2]), "+f"(c[3])
        : "r"(a[0]), "r"(a[1]), "r"(a[2]), "r"(a[3]), "r"(b[0]), "r"(b[1]));
}

__global__ __launch_bounds__(256, 2) void gemm_mma_kernel(
    const float* __restrict__ A,
    const float* __restrict__ W,
    const float* __restrict__ blin,
    __half* __restrict__ C,
    int M)
{
    extern __shared__ char smem[];
    const uint32_t sbase = smem_u32(smem);
    const int tid  = threadIdx.x;
    const int wid  = tid >> 5;
    const int lane = tid & 31;
    const int warp_m = wid & 3;       // 0..3 -> 32-row slice
    const int warp_n = wid >> 2;      // 0..1 -> 32-col slice
    const int bn = blockIdx.x * BN;   // fastest axis -> A-tile sharing in-wave
    const int bm = blockIdx.y * BM;

    float acc[2][4][4];
#pragma unroll
    for (int i = 0; i < 2; i++)
#pragma unroll
        for (int j = 0; j < 4; j++)
#pragma unroll
            for (int v = 0; v < 4; v++) acc[i][j][v] = 0.0f;

    // Staging coordinates
    const int arow0 = tid >> 4;
    const int aq    = (tid & 15) * 4;

    // ldmatrix per-lane offsets (within a buffer)
    const int a_row = warp_m * 32 + (lane & 15);
    const int a_col = (lane >> 4) * 8;
    const uint32_t a_off = AS + (uint32_t)(a_row * LDS + a_col) * 2;
    const int b_row_base = warp_n * 32 + ((lane >> 4) << 3) + (lane & 7);
    const int b_col = ((lane >> 3) & 1) * 8;
    const uint32_t b_off = BS + (uint32_t)(b_row_base * LDS + b_col) * 2;

    // ---- prologue: prefetch + convert chunk 0 into buffer 0 ----
    float4 av[8], wv[4];
#pragma unroll
    for (int k = 0; k < 8; k++) {
        const int gr = bm + arow0 + k * 16;
        av[k] = (gr < M)
            ? *reinterpret_cast<const float4*>(A + (size_t)gr * NN_D + aq)
            : make_float4(0.f, 0.f, 0.f, 0.f);
    }
#pragma unroll
    for (int k = 0; k < 4; k++) {
        wv[k] = *reinterpret_cast<const float4*>(
            W + (size_t)(bn + arow0 + k * 16) * NN_D + aq);
    }
#pragma unroll
    for (int k = 0; k < 8; k++) {
        const uint32_t off = (uint32_t)((arow0 + k * 16) * LDS + aq) * 2;
        *reinterpret_cast<uint2*>(smem + AS + off) =
            make_uint2(cvt_f16x2(av[k].x, av[k].y), cvt_f16x2(av[k].z, av[k].w));
    }
#pragma unroll
    for (int k = 0; k < 4; k++) {
        const uint32_t off = (uint32_t)((arow0 + k * 16) * LDS + aq) * 2;
        *reinterpret_cast<uint2*>(smem + BS + off) =
            make_uint2(cvt_f16x2(wv[k].x, wv[k].y), cvt_f16x2(wv[k].z, wv[k].w));
    }
    __syncthreads();

    for (int c = 0; c < NN_D / KC; c++) {        // 4 K-chunks
        const uint32_t cbuf = (uint32_t)(c & 1) * BUFB;
        const uint32_t nbuf = (uint32_t)((c + 1) & 1) * BUFB;
        const bool have_next = (c < NN_D / KC - 1);

        // ---- fire next chunk's LDGs early (latency covered by MMAs) ----
        if (have_next) {
            const int ko = (c + 1) * KC;
#pragma unroll
            for (int k = 0; k < 8; k++) {
                const int gr = bm + arow0 + k * 16;
                av[k] = (gr < M)
                    ? *reinterpret_cast<const float4*>(A + (size_t)gr * NN_D + ko + aq)
                    : make_float4(0.f, 0.f, 0.f, 0.f);
            }
#pragma unroll
            for (int k = 0; k < 4; k++) {
                wv[k] = *reinterpret_cast<const float4*>(
                    W + (size_t)(bn + arow0 + k * 16) * NN_D + ko + aq);
            }
        }

        // ---- compute on current buffer: 4 k-steps of 16 ----
#pragma unroll
        for (int ks = 0; ks < KC / 16; ks++) {
            const uint32_t koff = (uint32_t)(ks * 16) * 2;

            uint32_t af[2][4];
            ldm_x4(af[0][0], af[0][1], af[0][2], af[0][3], sbase + cbuf + a_off + koff);
            ldm_x4(af[1][0], af[1][1], af[1][2], af[1][3],
                   sbase + cbuf + a_off + koff + 16 * LDS * 2);

            uint32_t bf[4][2];
#pragma unroll
            for (int np = 0; np < 2; np++) {
                const uint32_t bo = sbase + cbuf + b_off + koff + (uint32_t)(np * 16 * LDS) * 2;
                ldm_x4(bf[2 * np][0], bf[2 * np][1], bf[2 * np + 1][0], bf[2 * np + 1][1], bo);
            }

#pragma unroll
            for (int mi = 0; mi < 2; mi++) {
#pragma unroll
                for (int nj = 0; nj < 4; nj++) {
                    mma16816(acc[mi][nj], af[mi], bf[nj]);
                }
            }
        }

        // ---- convert next chunk into the other buffer (no barrier needed:
        //      its previous readers were fenced by last iteration's sync) ----
        if (have_next) {
#pragma unroll
            for (int k = 0; k < 8; k++) {
                const uint32_t off = (uint32_t)((arow0 + k * 16) * LDS + aq) * 2;
                *reinterpret_cast<uint2*>(smem + nbuf + AS + off) =
                    make_uint2(cvt_f16x2(av[k].x, av[k].y), cvt_f16x2(av[k].z, av[k].w));
            }
#pragma unroll
            for (int k = 0; k < 4; k++) {
                const uint32_t off = (uint32_t)((arow0 + k * 16) * LDS + aq) * 2;
                *reinterpret_cast<uint2*>(smem + nbuf + BS + off) =
                    make_uint2(cvt_f16x2(wv[k].x, wv[k].y), cvt_f16x2(wv[k].z, wv[k].w));
            }
            __syncthreads();
        }
    }

    // ---- epilogue: + b_lin, store fp16 ----
    float2 blv[4];
#pragma unroll
    for (int nj = 0; nj < 4; nj++) {
        const int col = bn + warp_n * 32 + nj * 8 + (lane & 3) * 2;
        blv[nj].x = __ldg(blin + col);
        blv[nj].y = __ldg(blin + col + 1);
    }
#pragma unroll
    for (int mi = 0; mi < 2; mi++) {
        const int r0 = bm + warp_m * 32 + mi * 16 + (lane >> 2);
        const int r1 = r0 + 8;
#pragma unroll
        for (int nj = 0; nj < 4; nj++) {
            const int col = bn + warp_n * 32 + nj * 8 + (lane & 3) * 2;
            if (r0 < M) {
                *reinterpret_cast<__half2*>(C + (size_t)r0 * NN_D + col) =
                    __floats2half2_rn(acc[mi][nj][0] + blv[nj].x,
                                      acc[mi][nj][1] + blv[nj].y);
            }
            if (r1 < M) {
                *reinterpret_cast<__half2*>(C + (size_t)r1 * NN_D + col) =
                    __floats2half2_rn(acc[mi][nj][2] + blv[nj].x,
                                      acc[mi][nj][3] + blv[nj].y);
            }
        }
    }
}

// ---------------------------------------------------------------------------
// Aggregation: out[n][d] = tanh(sum_k sup[a2a[n][k]][d] * fe[n2e[n][k]][d]) + bias[d]
// support is fp16 (25.6 MB, L2-resident); fedges streamed evict-first.
// ---------------------------------------------------------------------------
struct alignas(8) half4 { __half2 a, b; };

__global__ __launch_bounds__(64) void agg_kernel(
    const __half* __restrict__ support,
    const float* __restrict__ fedges,
    const int* __restrict__ a2a,
    const int* __restrict__ n2e,
    const float* __restrict__ bias,
    float* __restrict__ out,
    int M)
{
    const int n = blockIdx.x;
    if (n >= M) return;

    __shared__ int sa[KNEI];
    __shared__ int se[KNEI];

    const int t = threadIdx.x;
    if (t < KNEI) {
        sa[t] = a2a[(size_t)n * KNEI + t];
    } else if (t < 2 * KNEI) {
        se[t - KNEI] = n2e[(size_t)n * KNEI + (t - KNEI)];
    }
    __syncthreads();

    const int off = t * 4;
    float4 acc = make_float4(0.f, 0.f, 0.f, 0.f);

#pragma unroll
    for (int k = 0; k < KNEI; k++) {
        const half4 s = *reinterpret_cast<const half4*>(
            &support[(size_t)sa[k] * NN_D + off]);
        const float4 f = __ldcs(reinterpret_cast<const float4*>(
            &fedges[(size_t)se[k] * NN_D + off]));
        const float2 s0 = __half22float2(s.a);
        const float2 s1 = __half22float2(s.b);
        acc.x += s0.x * f.x;
        acc.y += s0.y * f.y;
        acc.z += s1.x * f.z;
        acc.w += s1.y * f.w;
    }

    const float4 bl = *reinterpret_cast<const float4*>(&bias[off]);
    float4 o;
    o.x = tanhf(acc.x) + bl.x;
    o.y = tanhf(acc.y) + bl.y;
    o.z = tanhf(acc.z) + bl.z;
    o.w = tanhf(acc.w) + bl.w;
    __stcs(reinterpret_cast<float4*>(&out[(size_t)n * NN_D + off]), o);
}

// ---------------------------------------------------------------------------
// Launch
// ---------------------------------------------------------------------------
extern "C" void kernel_launch(void* const* d_in, const int* in_sizes, int n_in,
                              void* d_out, int out_size)
{
    const float* x    = (const float*)d_in[0];
    const float* fe   = (const float*)d_in[1];
    const int*   a2a  = (const int*)d_in[2];
    const int*   n2e  = (const int*)d_in[3];
    const float* W    = (const float*)d_in[4];
    const float* blin = (const float*)d_in[5];
    const float* bias = (const float*)d_in[6];
    float*       out  = (float*)d_out;

    const int M = in_sizes[0] / NN_D;               // 50000

    __half* sup = nullptr;
    cudaGetSymbolAddress((void**)&sup, g_support_h);

    cudaFuncSetAttribute(gemm_mma_kernel,
                         cudaFuncAttributeMaxDynamicSharedMemorySize, SMEM_GEMM);

    dim3 ggrid(NN_D / BN, (M + BM - 1) / BM);       // (4, 391) - bn fastest
    gemm_mma_kernel<<<ggrid, 256, SMEM_GEMM>>>(x, W, blin, sup, M);

    agg_kernel<<<M, 64>>>(sup, fe, a2a, n2e, bias, out, M);
}